// round 5
// baseline (speedup 1.0000x reference)
#include <cuda_runtime.h>
#include <cuda_bf16.h>
#include <math.h>
#include <stdint.h>

#define B 2
#define S 2048
#define D 768
#define H 12
#define E 64
#define BS (B*S)   // 4096
#define PAD 72     // bf16 elements per smem row (144 bytes) -> conflict-free ldmatrix

// ---- scratch (static device globals; no runtime allocation) ----
__device__ __align__(16) __nv_bfloat16 g_x_hi[(size_t)BS * D];
__device__ __align__(16) __nv_bfloat16 g_x_lo[(size_t)BS * D];
__device__ __align__(16) __nv_bfloat16 g_wt_hi[(size_t)3 * H * E * D]; // [which][h*E+e][k]
__device__ __align__(16) __nv_bfloat16 g_wt_lo[(size_t)3 * H * E * D];
__device__ __align__(16) __nv_bfloat16 g_wo_hi[(size_t)D * D];         // [n][k]
__device__ __align__(16) __nv_bfloat16 g_wo_lo[(size_t)D * D];
__device__ __align__(16) __nv_bfloat16 g_qkvb_hi[(size_t)3 * H * BS * E]; // [which][h][b*S+s][e]
__device__ __align__(16) __nv_bfloat16 g_qkvb_lo[(size_t)3 * H * BS * E];
__device__ __align__(16) __nv_bfloat16 g_att_hi[(size_t)BS * D];       // [b*S+s][h*E+e]
__device__ __align__(16) __nv_bfloat16 g_att_lo[(size_t)BS * D];

// ======================= helpers =======================
__device__ __forceinline__ uint32_t smem_u32(const void* p) {
    uint32_t a;
    asm("{ .reg .u64 t; cvta.to.shared.u64 t, %1; cvt.u32.u64 %0, t; }" : "=r"(a) : "l"(p));
    return a;
}
__device__ __forceinline__ void ldsm4(uint32_t* r, uint32_t a) {
    asm volatile("ldmatrix.sync.aligned.m8n8.x4.shared.b16 {%0,%1,%2,%3}, [%4];"
        : "=r"(r[0]), "=r"(r[1]), "=r"(r[2]), "=r"(r[3]) : "r"(a));
}
__device__ __forceinline__ void ldsm4t(uint32_t* r, uint32_t a) {
    asm volatile("ldmatrix.sync.aligned.m8n8.x4.trans.shared.b16 {%0,%1,%2,%3}, [%4];"
        : "=r"(r[0]), "=r"(r[1]), "=r"(r[2]), "=r"(r[3]) : "r"(a));
}
__device__ __forceinline__ void mma16816(float* c, const uint32_t* a, uint32_t b0, uint32_t b1) {
    asm volatile("mma.sync.aligned.m16n8k16.row.col.f32.bf16.bf16.f32 "
        "{%0,%1,%2,%3}, {%4,%5,%6,%7}, {%8,%9}, {%0,%1,%2,%3};"
        : "+f"(c[0]), "+f"(c[1]), "+f"(c[2]), "+f"(c[3])
        : "r"(a[0]), "r"(a[1]), "r"(a[2]), "r"(a[3]), "r"(b0), "r"(b1));
}
__device__ __forceinline__ void split2(float x, float y, uint32_t& hi, uint32_t& lo) {
    __nv_bfloat162 h = __floats2bfloat162_rn(x, y);
    float hx = __bfloat162float(h.x), hy = __bfloat162float(h.y);
    __nv_bfloat162 l = __floats2bfloat162_rn(x - hx, y - hy);
    hi = *(uint32_t*)&h; lo = *(uint32_t*)&l;
}
#define CP_COMMIT()  asm volatile("cp.async.commit_group;" ::: "memory")
#define CP_WAIT1()   asm volatile("cp.async.wait_group 1;" ::: "memory")
#define CP_WAIT0()   asm volatile("cp.async.wait_group 0;" ::: "memory")

// async copy of 128 rows x 64 bf16 (row stride ldg elems) into padded smem tile (256 thr)
__device__ __forceinline__ void load_tile_async(const __nv_bfloat16* __restrict__ g, int ldg,
                                                uint32_t sdst, int t)
{
    #pragma unroll
    for (int i = 0; i < 4; i++) {
        int f = i * 256 + t;
        int r = f >> 3, c8 = (f & 7) * 8;
        asm volatile("cp.async.cg.shared.global [%0], [%1], 16;"
            :: "r"(sdst + (uint32_t)(r * PAD + c8) * 2), "l"(g + (size_t)r * ldg + c8));
    }
}
// sync version (Q staging)
__device__ __forceinline__ void load_tile_pad(const __nv_bfloat16* __restrict__ g, int ldg,
                                              __nv_bfloat16* s, int t)
{
    #pragma unroll
    for (int i = 0; i < 4; i++) {
        int f = i * 256 + t;
        int r = f >> 3, c8 = (f & 7) * 8;
        *(uint4*)(s + r * PAD + c8) = *(const uint4*)(g + (size_t)r * ldg + c8);
    }
}

// ======================= prep: fp32 -> bf16 hi/lo =======================
__global__ void split_kernel(const float* __restrict__ src,
                             __nv_bfloat16* __restrict__ hi, __nv_bfloat16* __restrict__ lo, int n)
{
    int i = blockIdx.x * 256 + threadIdx.x;
    if (i < n) {
        float v = src[i];
        __nv_bfloat16 h = __float2bfloat16(v);
        hi[i] = h;
        lo[i] = __float2bfloat16(v - __bfloat162float(h));
    }
}
__global__ void wsplit_kernel(const float* __restrict__ W,
                              __nv_bfloat16* __restrict__ hi, __nv_bfloat16* __restrict__ lo)
{
    int idx = blockIdx.x * 256 + threadIdx.x;
    if (idx >= H * E * D) return;
    int k = idx % D, r = idx / D;
    int h = r / E, e = r % E;
    float v = W[((size_t)h * D + k) * E + e];
    __nv_bfloat16 hv = __float2bfloat16(v);
    hi[idx] = hv;
    lo[idx] = __float2bfloat16(v - __bfloat162float(hv));
}
__global__ void wosplit_kernel(const float* __restrict__ Wo,
                               __nv_bfloat16* __restrict__ hi, __nv_bfloat16* __restrict__ lo)
{
    int idx = blockIdx.x * 256 + threadIdx.x;
    if (idx >= D * D) return;
    int k = idx % D, n = idx / D;
    float v = Wo[(size_t)k * D + n];
    __nv_bfloat16 hv = __float2bfloat16(v);
    hi[idx] = hv;
    lo[idx] = __float2bfloat16(v - __bfloat162float(hv));
}

// ======================= shared GEMM core (mma.sync, cp.async double-buffered) ===========
// 256 threads, warp grid 4(M)x2(N); warp tile 32x64; CTA tile 128x128, k-chunk 64 x 12.
struct GemmAcc { float a[2][8][4]; };
#define TILE_B 18432            // one 128x72 bf16 tile
#define STAGE_B (4 * TILE_B)    // Ah,Al,Bh,Bl

__device__ __forceinline__ void gemm_chunks(
    const __nv_bfloat16* Ah_g, const __nv_bfloat16* Al_g, int lda,
    const __nv_bfloat16* Bh_g, const __nv_bfloat16* Bl_g, int ldb,
    char* smem, int t, GemmAcc& C)
{
    const uint32_t sb = smem_u32(smem);
    const int lane = t & 31, wid = t >> 5;
    const int mrow0 = (wid >> 1) * 32;
    const int ncol0 = (wid & 1) * 64;

    const uint32_t a_off = (uint32_t)(mrow0 + (lane & 15)) * 144 + ((lane & 16) >> 1) * 2;
    const uint32_t b_off = (uint32_t)(ncol0 + (lane & 7) + ((lane & 16) >> 1)) * 144 + (lane & 8) * 2;

    // prefetch chunk 0 -> stage 0
    load_tile_async(Ah_g, lda, sb + 0 * TILE_B, t);
    load_tile_async(Al_g, lda, sb + 1 * TILE_B, t);
    load_tile_async(Bh_g, ldb, sb + 2 * TILE_B, t);
    load_tile_async(Bl_g, ldb, sb + 3 * TILE_B, t);
    CP_COMMIT();

    #pragma unroll 1
    for (int c = 0; c < 12; c++) {
        if (c + 1 < 12) {
            const uint32_t ns = sb + ((c + 1) & 1) * STAGE_B;
            load_tile_async(Ah_g + (c + 1) * 64, lda, ns + 0 * TILE_B, t);
            load_tile_async(Al_g + (c + 1) * 64, lda, ns + 1 * TILE_B, t);
            load_tile_async(Bh_g + (c + 1) * 64, ldb, ns + 2 * TILE_B, t);
            load_tile_async(Bl_g + (c + 1) * 64, ldb, ns + 3 * TILE_B, t);
            CP_COMMIT();
            CP_WAIT1();
        } else {
            CP_WAIT0();
        }
        __syncthreads();

        const uint32_t cs = sb + (c & 1) * STAGE_B;
        const uint32_t uAh = cs, uAl = cs + TILE_B, uBh = cs + 2 * TILE_B, uBl = cs + 3 * TILE_B;

        #pragma unroll
        for (int ks = 0; ks < 4; ks++) {
            uint32_t ah0[4], ah1[4], al0[4], al1[4];
            const uint32_t ao = a_off + ks * 32;
            ldsm4(ah0, uAh + ao);
            ldsm4(ah1, uAh + ao + 16 * 144);
            ldsm4(al0, uAl + ao);
            ldsm4(al1, uAl + ao + 16 * 144);
            #pragma unroll
            for (int np = 0; np < 4; np++) {
                uint32_t bh[4], bl[4];
                const uint32_t bo = b_off + np * 16 * 144 + ks * 32;
                ldsm4(bh, uBh + bo);
                ldsm4(bl, uBl + bo);
                mma16816(C.a[0][2*np],   ah0, bh[0], bh[1]);
                mma16816(C.a[0][2*np],   ah0, bl[0], bl[1]);
                mma16816(C.a[0][2*np],   al0, bh[0], bh[1]);
                mma16816(C.a[0][2*np+1], ah0, bh[2], bh[3]);
                mma16816(C.a[0][2*np+1], ah0, bl[2], bl[3]);
                mma16816(C.a[0][2*np+1], al0, bh[2], bh[3]);
                mma16816(C.a[1][2*np],   ah1, bh[0], bh[1]);
                mma16816(C.a[1][2*np],   ah1, bl[0], bl[1]);
                mma16816(C.a[1][2*np],   al1, bh[0], bh[1]);
                mma16816(C.a[1][2*np+1], ah1, bh[2], bh[3]);
                mma16816(C.a[1][2*np+1], ah1, bl[2], bl[3]);
                mma16816(C.a[1][2*np+1], al1, bh[2], bh[3]);
            }
        }
        __syncthreads();
    }
}

// ======================= QKV GEMM kernel =======================
__global__ __launch_bounds__(256) void qkv_mma_kernel(
    const float* __restrict__ bq, const float* __restrict__ bk, const float* __restrict__ bv)
{
    extern __shared__ __align__(16) char smem[];
    const int t = threadIdx.x, lane = t & 31, wid = t >> 5;
    const int m0 = blockIdx.x * 128;
    const int zz = blockIdx.y;
    const int which = zz / (H / 2);
    const int h0 = (zz % (H / 2)) * 2;

    GemmAcc C;
    #pragma unroll
    for (int i = 0; i < 2; i++)
        #pragma unroll
        for (int j = 0; j < 8; j++)
            C.a[i][j][0] = C.a[i][j][1] = C.a[i][j][2] = C.a[i][j][3] = 0.f;

    gemm_chunks(g_x_hi + (size_t)m0 * D, g_x_lo + (size_t)m0 * D, D,
                g_wt_hi + ((size_t)which * H + h0) * E * D,
                g_wt_lo + ((size_t)which * H + h0) * E * D, D,
                smem, t, C);

    const float* bias = (which == 0) ? bq : (which == 1) ? bk : bv;
    const int g = lane >> 2, j2 = (lane & 3) * 2;
    const int mrow0 = (wid >> 1) * 32, ncol0 = (wid & 1) * 64;
    __nv_bfloat16* dh = g_qkvb_hi;
    __nv_bfloat16* dl = g_qkvb_lo;

    #pragma unroll
    for (int mi = 0; mi < 2; mi++) {
        const int mA = m0 + mrow0 + mi * 16 + g;
        #pragma unroll
        for (int nt = 0; nt < 8; nt++) {
            const int n = ncol0 + nt * 8 + j2;
            const int hh = h0 + (n >> 6), e = n & 63;
            const float b0f = bias[hh * E + e], b1f = bias[hh * E + e + 1];
            size_t base = ((size_t)which * H + hh) * BS * E + e;
            uint32_t hi, lo;
            split2(C.a[mi][nt][0] + b0f, C.a[mi][nt][1] + b1f, hi, lo);
            *(uint32_t*)(dh + base + (size_t)mA * E) = hi;
            *(uint32_t*)(dl + base + (size_t)mA * E) = lo;
            split2(C.a[mi][nt][2] + b0f, C.a[mi][nt][3] + b1f, hi, lo);
            *(uint32_t*)(dh + base + (size_t)(mA + 8) * E) = hi;
            *(uint32_t*)(dl + base + (size_t)(mA + 8) * E) = lo;
        }
    }
}

// ======================= output projection kernel =======================
__global__ __launch_bounds__(256) void proj_mma_kernel(
    const float* __restrict__ bo, float* __restrict__ out)
{
    extern __shared__ __align__(16) char smem[];
    const int t = threadIdx.x, lane = t & 31, wid = t >> 5;
    const int m0 = blockIdx.x * 128;
    const int n0 = blockIdx.y * 128;

    GemmAcc C;
    #pragma unroll
    for (int i = 0; i < 2; i++)
        #pragma unroll
        for (int j = 0; j < 8; j++)
            C.a[i][j][0] = C.a[i][j][1] = C.a[i][j][2] = C.a[i][j][3] = 0.f;

    gemm_chunks(g_att_hi + (size_t)m0 * D, g_att_lo + (size_t)m0 * D, D,
                g_wo_hi + (size_t)n0 * D, g_wo_lo + (size_t)n0 * D, D,
                smem, t, C);

    const int g = lane >> 2, j2 = (lane & 3) * 2;
    const int mrow0 = (wid >> 1) * 32, ncol0 = (wid & 1) * 64;

    #pragma unroll
    for (int mi = 0; mi < 2; mi++) {
        const int mA = m0 + mrow0 + mi * 16 + g;
        #pragma unroll
        for (int nt = 0; nt < 8; nt++) {
            const int n = n0 + ncol0 + nt * 8 + j2;
            const float b0f = bo[n], b1f = bo[n + 1];
            float2 v0 = { C.a[mi][nt][0] + b0f, C.a[mi][nt][1] + b1f };
            float2 v1 = { C.a[mi][nt][2] + b0f, C.a[mi][nt][3] + b1f };
            *(float2*)(out + (size_t)mA * D + n) = v0;
            *(float2*)(out + (size_t)(mA + 8) * D + n) = v1;
        }
    }
}

// ======================= flash attention (mma.sync, cp.async pipelined) =======================
// 256 threads, 8 warps; warp tile 16(q) x 128(kv). q-tile 128, kv chunks of 128.
// smem: 2 stages x {Kh,Kl,Vh,Vl} x 18432 B = 147456 B. Q staged in stage0 before mainloop.
__global__ __launch_bounds__(256) void attn_kernel(const float* __restrict__ mask_all)
{
    extern __shared__ __align__(16) char smem[];
    const uint32_t sb = smem_u32(smem);

    const int q0 = blockIdx.x * 128;
    const int hb = blockIdx.y;
    const int h = hb / B, b = hb % B;

    const __nv_bfloat16* Qh_g = g_qkvb_hi + ((size_t)0 * H + h) * BS * E + (size_t)(b * S + q0) * E;
    const __nv_bfloat16* Ql_g = g_qkvb_lo + ((size_t)0 * H + h) * BS * E + (size_t)(b * S + q0) * E;
    const __nv_bfloat16* Kh_g = g_qkvb_hi + ((size_t)1 * H + h) * BS * E + (size_t)b * S * E;
    const __nv_bfloat16* Kl_g = g_qkvb_lo + ((size_t)1 * H + h) * BS * E + (size_t)b * S * E;
    const __nv_bfloat16* Vh_g = g_qkvb_hi + ((size_t)2 * H + h) * BS * E + (size_t)b * S * E;
    const __nv_bfloat16* Vl_g = g_qkvb_lo + ((size_t)2 * H + h) * BS * E + (size_t)b * S * E;
    const float* mask = mask_all + (size_t)(h * B + b) * S * S;

    const int t = threadIdx.x, lane = t & 31, wid = t >> 5;
    const int g = lane >> 2, j2 = (lane & 3) * 2;
    const int r0 = wid * 16;

    // ---- Q -> stage0 smem -> register fragments ----
    load_tile_pad(Qh_g, E, (__nv_bfloat16*)(smem), t);
    load_tile_pad(Ql_g, E, (__nv_bfloat16*)(smem + TILE_B), t);
    __syncthreads();
    uint32_t qh[4][4], ql[4][4];
    {
        const uint32_t ao = (uint32_t)(r0 + (lane & 15)) * 144 + ((lane & 16) >> 1) * 2;
        #pragma unroll
        for (int ks = 0; ks < 4; ks++) {
            ldsm4(qh[ks], sb + ao + ks * 32);
            ldsm4(ql[ks], sb + TILE_B + ao + ks * 32);
        }
    }
    __syncthreads();   // all warps done with Q staging before prefetch overwrites

    float m_a = -INFINITY, m_b = -INFINITY, l_a = 0.f, l_b = 0.f;
    float o[8][4];
    #pragma unroll
    for (int et = 0; et < 8; et++)
        o[et][0] = o[et][1] = o[et][2] = o[et][3] = 0.f;

    const uint32_t kb_off = (uint32_t)((lane & 7) + ((lane & 16) >> 1)) * 144 + (lane & 8) * 2;
    const uint32_t vb_off = (uint32_t)(lane & 15) * 144 + ((lane & 16) >> 1) * 2;

    // prefetch chunk 0 -> stage 0
    load_tile_async(Kh_g, E, sb + 0 * TILE_B, t);
    load_tile_async(Kl_g, E, sb + 1 * TILE_B, t);
    load_tile_async(Vh_g, E, sb + 2 * TILE_B, t);
    load_tile_async(Vl_g, E, sb + 3 * TILE_B, t);
    CP_COMMIT();

    #pragma unroll 1
    for (int jc = 0; jc < 16; jc++) {
        const int j0 = jc * 128;
        if (jc + 1 < 16) {
            const uint32_t ns = sb + ((jc + 1) & 1) * STAGE_B;
            const size_t go = (size_t)(j0 + 128) * E;
            load_tile_async(Kh_g + go, E, ns + 0 * TILE_B, t);
            load_tile_async(Kl_g + go, E, ns + 1 * TILE_B, t);
            load_tile_async(Vh_g + go, E, ns + 2 * TILE_B, t);
            load_tile_async(Vl_g + go, E, ns + 3 * TILE_B, t);
            CP_COMMIT();
            CP_WAIT1();
        } else {
            CP_WAIT0();
        }
        __syncthreads();

        const uint32_t cs = sb + (jc & 1) * STAGE_B;
        const uint32_t uKh = cs, uKl = cs + TILE_B, uVh = cs + 2 * TILE_B, uVl = cs + 3 * TILE_B;

        // ---- mask L2 prefetch (overlaps the S-MMA block) ----
        const float* mra = mask + (size_t)(q0 + r0 + g) * S + j0 + j2;
        const float* mrb = mra + 8 * S;
        #pragma unroll
        for (int q8 = 0; q8 < 4; q8++) {
            asm volatile("prefetch.global.L2 [%0];" :: "l"(mra + q8 * 32));
            asm volatile("prefetch.global.L2 [%0];" :: "l"(mrb + q8 * 32));
        }

        // ---- S = Q K^T (hi/lo 3-product) ----
        float s[16][4];
        #pragma unroll
        for (int nt = 0; nt < 16; nt++)
            s[nt][0] = s[nt][1] = s[nt][2] = s[nt][3] = 0.f;

        #pragma unroll
        for (int ks = 0; ks < 4; ks++) {
            #pragma unroll
            for (int np = 0; np < 8; np++) {
                uint32_t bh[4], bl[4];
                const uint32_t bo = kb_off + np * 16 * 144 + ks * 32;
                ldsm4(bh, uKh + bo);
                ldsm4(bl, uKl + bo);
                mma16816(s[2*np],   qh[ks], bh[0], bh[1]);
                mma16816(s[2*np],   qh[ks], bl[0], bl[1]);
                mma16816(s[2*np],   ql[ks], bh[0], bh[1]);
                mma16816(s[2*np+1], qh[ks], bh[2], bh[3]);
                mma16816(s[2*np+1], qh[ks], bl[2], bl[3]);
                mma16816(s[2*np+1], ql[ks], bh[2], bh[3]);
            }
        }

        // ---- additive mask (L2 hits thanks to prefetch) ----
        #pragma unroll
        for (int nt = 0; nt < 16; nt++) {
            float2 ma = *(const float2*)(mra + nt * 8);
            float2 mb = *(const float2*)(mrb + nt * 8);
            s[nt][0] += ma.x; s[nt][1] += ma.y;
            s[nt][2] += mb.x; s[nt][3] += mb.y;
        }

        // ---- online softmax (rows g and g+8) ----
        float mxa = -INFINITY, mxb = -INFINITY;
        #pragma unroll
        for (int nt = 0; nt < 16; nt++) {
            mxa = fmaxf(mxa, fmaxf(s[nt][0], s[nt][1]));
            mxb = fmaxf(mxb, fmaxf(s[nt][2], s[nt][3]));
        }
        mxa = fmaxf(mxa, __shfl_xor_sync(0xffffffffu, mxa, 1));
        mxa = fmaxf(mxa, __shfl_xor_sync(0xffffffffu, mxa, 2));
        mxb = fmaxf(mxb, __shfl_xor_sync(0xffffffffu, mxb, 1));
        mxb = fmaxf(mxb, __shfl_xor_sync(0xffffffffu, mxb, 2));

        const float mna = fmaxf(m_a, mxa), mnb = fmaxf(m_b, mxb);
        const float aa = __expf(m_a - mna), ab = __expf(m_b - mnb);
        float sa = 0.f, sb2 = 0.f;
        #pragma unroll
        for (int nt = 0; nt < 16; nt++) {
            s[nt][0] = __expf(s[nt][0] - mna); sa += s[nt][0];
            s[nt][1] = __expf(s[nt][1] - mna); sa += s[nt][1];
            s[nt][2] = __expf(s[nt][2] - mnb); sb2 += s[nt][2];
            s[nt][3] = __expf(s[nt][3] - mnb); sb2 += s[nt][3];
        }
        sa  += __shfl_xor_sync(0xffffffffu, sa, 1);
        sa  += __shfl_xor_sync(0xffffffffu, sa, 2);
        sb2 += __shfl_xor_sync(0xffffffffu, sb2, 1);
        sb2 += __shfl_xor_sync(0xffffffffu, sb2, 2);
        l_a = l_a * aa + sa; l_b = l_b * ab + sb2;
        m_a = mna; m_b = mnb;
        #pragma unroll
        for (int et = 0; et < 8; et++) {
            o[et][0] *= aa; o[et][1] *= aa;
            o[et][2] *= ab; o[et][3] *= ab;
        }

        // ---- O += P V (P split hi/lo on the fly) ----
        #pragma unroll
        for (int ks2 = 0; ks2 < 8; ks2++) {
            const int nt0 = 2 * ks2, nt1 = nt0 + 1;
            uint32_t a_hi[4], a_lo[4];
            split2(s[nt0][0], s[nt0][1], a_hi[0], a_lo[0]);
            split2(s[nt0][2], s[nt0][3], a_hi[1], a_lo[1]);
            split2(s[nt1][0], s[nt1][1], a_hi[2], a_lo[2]);
            split2(s[nt1][2], s[nt1][3], a_hi[3], a_lo[3]);
            #pragma unroll
            for (int ep = 0; ep < 4; ep++) {
                uint32_t vh[4], vl[4];
                const uint32_t vo = vb_off + ks2 * 16 * 144 + ep * 32;
                ldsm4t(vh, uVh + vo);
                ldsm4t(vl, uVl + vo);
                mma16816(o[2*ep],   a_hi, vh[0], vh[1]);
                mma16816(o[2*ep],   a_lo, vh[0], vh[1]);
                mma16816(o[2*ep],   a_hi, vl[0], vl[1]);
                mma16816(o[2*ep+1], a_hi, vh[2], vh[3]);
                mma16816(o[2*ep+1], a_lo, vh[2], vh[3]);
                mma16816(o[2*ep+1], a_hi, vl[2], vl[3]);
            }
        }
        __syncthreads();
    }

    // ---- epilogue: normalize, split hi/lo, concat-head layout ----
    const float ia = 1.f / l_a, ib = 1.f / l_b;
    const int rowA = q0 + r0 + g, rowB = rowA + 8;
    #pragma unroll
    for (int et = 0; et < 8; et++) {
        const size_t col = (size_t)h * E + et * 8 + j2;
        uint32_t hi, lo;
        split2(o[et][0] * ia, o[et][1] * ia, hi, lo);
        *(uint32_t*)(g_att_hi + (size_t)(b * S + rowA) * D + col) = hi;
        *(uint32_t*)(g_att_lo + (size_t)(b * S + rowA) * D + col) = lo;
        split2(o[et][2] * ib, o[et][3] * ib, hi, lo);
        *(uint32_t*)(g_att_hi + (size_t)(b * S + rowB) * D + col) = hi;
        *(uint32_t*)(g_att_lo + (size_t)(b * S + rowB) * D + col) = lo;
    }
}

// ======================= Launch =======================
extern "C" void kernel_launch(void* const* d_in, const int* in_sizes, int n_in,
                              void* d_out, int out_size)
{
    const float* x    = (const float*)d_in[0];
    const float* mask = (const float*)d_in[1];
    const float* Wq   = (const float*)d_in[2];
    const float* bq   = (const float*)d_in[3];
    const float* Wk   = (const float*)d_in[4];
    const float* bk   = (const float*)d_in[5];
    const float* Wv   = (const float*)d_in[6];
    const float* bv   = (const float*)d_in[7];
    const float* Wo   = (const float*)d_in[8];
    const float* bo   = (const float*)d_in[9];

    __nv_bfloat16 *xhi, *xlo, *wthi, *wtlo, *wohi, *wolo;
    cudaGetSymbolAddress((void**)&xhi,  g_x_hi);
    cudaGetSymbolAddress((void**)&xlo,  g_x_lo);
    cudaGetSymbolAddress((void**)&wthi, g_wt_hi);
    cudaGetSymbolAddress((void**)&wtlo, g_wt_lo);
    cudaGetSymbolAddress((void**)&wohi, g_wo_hi);
    cudaGetSymbolAddress((void**)&wolo, g_wo_lo);

    const int smem_pipe = 2 * STAGE_B;   // 147,456 B (gemm + attn)
    cudaFuncSetAttribute(qkv_mma_kernel,  cudaFuncAttributeMaxDynamicSharedMemorySize, smem_pipe);
    cudaFuncSetAttribute(proj_mma_kernel, cudaFuncAttributeMaxDynamicSharedMemorySize, smem_pipe);
    cudaFuncSetAttribute(attn_kernel,     cudaFuncAttributeMaxDynamicSharedMemorySize, smem_pipe);

    const size_t HED = (size_t)H * E * D;
    split_kernel  <<< (BS * D + 255) / 256, 256 >>>(x, xhi, xlo, BS * D);
    wsplit_kernel <<< (H * E * D + 255) / 256, 256 >>>(Wq, wthi + 0 * HED, wtlo + 0 * HED);
    wsplit_kernel <<< (H * E * D + 255) / 256, 256 >>>(Wk, wthi + 1 * HED, wtlo + 1 * HED);
    wsplit_kernel <<< (H * E * D + 255) / 256, 256 >>>(Wv, wthi + 2 * HED, wtlo + 2 * HED);
    wosplit_kernel<<< (D * D + 255) / 256, 256 >>>(Wo, wohi, wolo);

    qkv_mma_kernel <<< dim3(BS / 128, 3 * (H / 2)), 256, smem_pipe >>>(bq, bk, bv);
    attn_kernel    <<< dim3(S / 128, H * B), 256, smem_pipe >>>(mask);
    proj_mma_kernel<<< dim3(BS / 128, D / 128), 256, smem_pipe >>>(bo, (float*)d_out);
}

// round 6
// speedup vs baseline: 1.0411x; 1.0411x over previous
#include <cuda_runtime.h>
#include <cuda_fp16.h>
#include <math.h>
#include <stdint.h>

#define B 2
#define S 2048
#define D 768
#define H 12
#define E 64
#define BS (B*S)   // 4096
#define PAD 72     // fp16 elements per smem row (144 bytes) -> conflict-free ldmatrix
#define XN (BS*D)
#define HED (H*E*D)

// ---- scratch (static device globals; no runtime allocation) ----
__device__ __align__(16) __half g_x_hi[(size_t)BS * D];
__device__ __align__(16) __half g_x_lo[(size_t)BS * D];
__device__ __align__(16) __half g_wt_hi[(size_t)3 * H * E * D]; // [which][h*E+e][k]
__device__ __align__(16) __half g_wt_lo[(size_t)3 * H * E * D];
__device__ __align__(16) __half g_wo_hi[(size_t)D * D];         // [n][k]
__device__ __align__(16) __half g_wo_lo[(size_t)D * D];
__device__ __align__(16) __half g_qkvb_hi[(size_t)3 * H * BS * E]; // [which][h][b*S+s][e]
__device__ __align__(16) __half g_qkvb_lo[(size_t)3 * H * BS * E];
__device__ __align__(16) __half g_att_hi[(size_t)BS * D];       // [b*S+s][h*E+e]
__device__ __align__(16) __half g_att_lo[(size_t)BS * D];

// ======================= helpers =======================
__device__ __forceinline__ uint32_t smem_u32(const void* p) {
    uint32_t a;
    asm("{ .reg .u64 t; cvta.to.shared.u64 t, %1; cvt.u32.u64 %0, t; }" : "=r"(a) : "l"(p));
    return a;
}
__device__ __forceinline__ void ldsm4(uint32_t* r, uint32_t a) {
    asm volatile("ldmatrix.sync.aligned.m8n8.x4.shared.b16 {%0,%1,%2,%3}, [%4];"
        : "=r"(r[0]), "=r"(r[1]), "=r"(r[2]), "=r"(r[3]) : "r"(a));
}
__device__ __forceinline__ void ldsm4t(uint32_t* r, uint32_t a) {
    asm volatile("ldmatrix.sync.aligned.m8n8.x4.trans.shared.b16 {%0,%1,%2,%3}, [%4];"
        : "=r"(r[0]), "=r"(r[1]), "=r"(r[2]), "=r"(r[3]) : "r"(a));
}
__device__ __forceinline__ void mma16816(float* c, const uint32_t* a, uint32_t b0, uint32_t b1) {
    asm volatile("mma.sync.aligned.m16n8k16.row.col.f32.f16.f16.f32 "
        "{%0,%1,%2,%3}, {%4,%5,%6,%7}, {%8,%9}, {%0,%1,%2,%3};"
        : "+f"(c[0]), "+f"(c[1]), "+f"(c[2]), "+f"(c[3])
        : "r"(a[0]), "r"(a[1]), "r"(a[2]), "r"(a[3]), "r"(b0), "r"(b1));
}
__device__ __forceinline__ void split2(float x, float y, uint32_t& hi, uint32_t& lo) {
    __half2 h = __floats2half2_rn(x, y);
    float hx = __low2float(h), hy = __high2float(h);
    __half2 l = __floats2half2_rn(x - hx, y - hy);
    hi = *(uint32_t*)&h; lo = *(uint32_t*)&l;
}

// sync copy of 128 rows x 64 fp16 (row stride ldg elems) into padded smem tile (256 thr)
__device__ __forceinline__ void load_tile_pad(const __half* __restrict__ g, int ldg,
                                              __half* s, int t)
{
    #pragma unroll
    for (int i = 0; i < 4; i++) {
        int f = i * 256 + t;
        int r = f >> 3, c8 = (f & 7) * 8;
        *(uint4*)(s + r * PAD + c8) = *(const uint4*)(g + (size_t)r * ldg + c8);
    }
}

// ======================= fused prep: fp32 -> fp16 hi/lo (all tensors) =======================
__global__ void prep_kernel(const float* __restrict__ x,
                            const float* __restrict__ Wq, const float* __restrict__ Wk,
                            const float* __restrict__ Wv, const float* __restrict__ Wo)
{
    int i = blockIdx.x * 256 + threadIdx.x;
    float v;
    __half *dh, *dl;
    if (i < XN) {
        v = x[i];
        dh = g_x_hi + i; dl = g_x_lo + i;
    } else if (i < XN + 3 * HED) {
        int i2 = i - XN;
        int w = i2 / HED, r2 = i2 % HED;
        int k = r2 % D, row = r2 / D;
        int h = row / E, e = row % E;
        const float* W = (w == 0) ? Wq : (w == 1) ? Wk : Wv;
        v = W[((size_t)h * D + k) * E + e];
        dh = g_wt_hi + i2; dl = g_wt_lo + i2;
    } else if (i < XN + 3 * HED + D * D) {
        int i3 = i - XN - 3 * HED;
        int k = i3 % D, n = i3 / D;
        v = Wo[(size_t)k * D + n];
        dh = g_wo_hi + i3; dl = g_wo_lo + i3;
    } else return;
    __half hv = __float2half_rn(v);
    *dh = hv;
    *dl = __float2half_rn(v - __half2float(hv));
}

// ======================= shared GEMM core (mma.sync, R4 sync-load structure) =======
// 256 threads, warp grid 4(M)x2(N); warp tile 32x64; CTA tile 128x128, k-chunk 64 x 12.
// use_blo: include A_hi x B_lo product (3-product) or not (2-product).
struct GemmAcc { float a[2][8][4]; };

__device__ __forceinline__ void gemm_chunks(
    const __half* Ah_g, const __half* Al_g, int lda,
    const __half* Bh_g, const __half* Bl_g, int ldb,
    char* smem, int t, GemmAcc& C, bool use_blo)
{
    __half* sAh = (__half*)(smem);
    __half* sAl = (__half*)(smem + 18432);
    __half* sBh = (__half*)(smem + 36864);
    __half* sBl = (__half*)(smem + 55296);
    const uint32_t uAh = smem_u32(sAh), uAl = smem_u32(sAl);
    const uint32_t uBh = smem_u32(sBh), uBl = smem_u32(sBl);

    const int lane = t & 31, wid = t >> 5;
    const int mrow0 = (wid >> 1) * 32;
    const int ncol0 = (wid & 1) * 64;

    const uint32_t a_off = (uint32_t)(mrow0 + (lane & 15)) * 144 + ((lane & 16) >> 1) * 2;
    const uint32_t b_off = (uint32_t)(ncol0 + (lane & 7) + ((lane & 16) >> 1)) * 144 + (lane & 8) * 2;

    #pragma unroll 1
    for (int c = 0; c < 12; c++) {
        __syncthreads();
        load_tile_pad(Ah_g + c * 64, lda, sAh, t);
        load_tile_pad(Al_g + c * 64, lda, sAl, t);
        load_tile_pad(Bh_g + c * 64, ldb, sBh, t);
        if (use_blo) load_tile_pad(Bl_g + c * 64, ldb, sBl, t);
        __syncthreads();

        #pragma unroll
        for (int ks = 0; ks < 4; ks++) {
            uint32_t ah0[4], ah1[4], al0[4], al1[4];
            const uint32_t ao = a_off + ks * 32;
            ldsm4(ah0, uAh + ao);
            ldsm4(ah1, uAh + ao + 16 * 144);
            ldsm4(al0, uAl + ao);
            ldsm4(al1, uAl + ao + 16 * 144);
            #pragma unroll
            for (int np = 0; np < 4; np++) {
                uint32_t bh[4];
                const uint32_t bo = b_off + np * 16 * 144 + ks * 32;
                ldsm4(bh, uBh + bo);
                mma16816(C.a[0][2*np],   ah0, bh[0], bh[1]);
                mma16816(C.a[0][2*np],   al0, bh[0], bh[1]);
                mma16816(C.a[0][2*np+1], ah0, bh[2], bh[3]);
                mma16816(C.a[0][2*np+1], al0, bh[2], bh[3]);
                mma16816(C.a[1][2*np],   ah1, bh[0], bh[1]);
                mma16816(C.a[1][2*np],   al1, bh[0], bh[1]);
                mma16816(C.a[1][2*np+1], ah1, bh[2], bh[3]);
                mma16816(C.a[1][2*np+1], al1, bh[2], bh[3]);
                if (use_blo) {
                    uint32_t bl[4];
                    ldsm4(bl, uBl + bo);
                    mma16816(C.a[0][2*np],   ah0, bl[0], bl[1]);
                    mma16816(C.a[0][2*np+1], ah0, bl[2], bl[3]);
                    mma16816(C.a[1][2*np],   ah1, bl[0], bl[1]);
                    mma16816(C.a[1][2*np+1], ah1, bl[2], bl[3]);
                }
            }
        }
    }
}

// ======================= QKV GEMM kernel =======================
__global__ __launch_bounds__(256) void qkv_mma_kernel(
    const float* __restrict__ bq, const float* __restrict__ bk, const float* __restrict__ bv)
{
    extern __shared__ __align__(16) char smem[];
    const int t = threadIdx.x, lane = t & 31, wid = t >> 5;
    const int m0 = blockIdx.x * 128;
    const int zz = blockIdx.y;
    const int which = zz / (H / 2);
    const int h0 = (zz % (H / 2)) * 2;

    GemmAcc C;
    #pragma unroll
    for (int i = 0; i < 2; i++)
        #pragma unroll
        for (int j = 0; j < 8; j++)
            C.a[i][j][0] = C.a[i][j][1] = C.a[i][j][2] = C.a[i][j][3] = 0.f;

    // Q,K need the full 3-product chain (feeds exp); V only needs relative precision.
    gemm_chunks(g_x_hi + (size_t)m0 * D, g_x_lo + (size_t)m0 * D, D,
                g_wt_hi + ((size_t)which * H + h0) * E * D,
                g_wt_lo + ((size_t)which * H + h0) * E * D, D,
                smem, t, C, which != 2);

    const float* bias = (which == 0) ? bq : (which == 1) ? bk : bv;
    const int g = lane >> 2, j2 = (lane & 3) * 2;
    const int mrow0 = (wid >> 1) * 32, ncol0 = (wid & 1) * 64;

    #pragma unroll
    for (int mi = 0; mi < 2; mi++) {
        const int mA = m0 + mrow0 + mi * 16 + g;
        #pragma unroll
        for (int nt = 0; nt < 8; nt++) {
            const int n = ncol0 + nt * 8 + j2;
            const int hh = h0 + (n >> 6), e = n & 63;
            const float b0f = bias[hh * E + e], b1f = bias[hh * E + e + 1];
            size_t base = ((size_t)which * H + hh) * BS * E + e;
            uint32_t hi, lo;
            split2(C.a[mi][nt][0] + b0f, C.a[mi][nt][1] + b1f, hi, lo);
            *(uint32_t*)(g_qkvb_hi + base + (size_t)mA * E) = hi;
            *(uint32_t*)(g_qkvb_lo + base + (size_t)mA * E) = lo;
            split2(C.a[mi][nt][2] + b0f, C.a[mi][nt][3] + b1f, hi, lo);
            *(uint32_t*)(g_qkvb_hi + base + (size_t)(mA + 8) * E) = hi;
            *(uint32_t*)(g_qkvb_lo + base + (size_t)(mA + 8) * E) = lo;
        }
    }
}

// ======================= output projection kernel (2-product) =======================
__global__ __launch_bounds__(256) void proj_mma_kernel(
    const float* __restrict__ bo, float* __restrict__ out)
{
    extern __shared__ __align__(16) char smem[];
    const int t = threadIdx.x, lane = t & 31, wid = t >> 5;
    const int m0 = blockIdx.x * 128;
    const int n0 = blockIdx.y * 128;

    GemmAcc C;
    #pragma unroll
    for (int i = 0; i < 2; i++)
        #pragma unroll
        for (int j = 0; j < 8; j++)
            C.a[i][j][0] = C.a[i][j][1] = C.a[i][j][2] = C.a[i][j][3] = 0.f;

    gemm_chunks(g_att_hi + (size_t)m0 * D, g_att_lo + (size_t)m0 * D, D,
                g_wo_hi + (size_t)n0 * D, g_wo_lo + (size_t)n0 * D, D,
                smem, t, C, false);

    const int g = lane >> 2, j2 = (lane & 3) * 2;
    const int mrow0 = (wid >> 1) * 32, ncol0 = (wid & 1) * 64;

    #pragma unroll
    for (int mi = 0; mi < 2; mi++) {
        const int mA = m0 + mrow0 + mi * 16 + g;
        #pragma unroll
        for (int nt = 0; nt < 8; nt++) {
            const int n = n0 + ncol0 + nt * 8 + j2;
            const float b0f = bo[n], b1f = bo[n + 1];
            float2 v0 = { C.a[mi][nt][0] + b0f, C.a[mi][nt][1] + b1f };
            float2 v1 = { C.a[mi][nt][2] + b0f, C.a[mi][nt][3] + b1f };
            *(float2*)(out + (size_t)mA * D + n) = v0;
            *(float2*)(out + (size_t)(mA + 8) * D + n) = v1;
        }
    }
}

// ======================= flash attention (mma.sync) =======================
// 256 threads, 8 warps; warp tile 16(q) x 128(kv). q-tile 128, kv chunks of 128.
// S = QK^T: 3-product (qh*kh + qh*kl + ql*kh). PV: 2-product (Ph*Vh + Pl*Vh).
// smem: Qh,Ql,Kh,Kl,Vh = 5 x 18432 B = 92160 B.
__global__ __launch_bounds__(256) void attn_kernel(const float* __restrict__ mask_all)
{
    extern __shared__ __align__(16) char smem[];
    __half* sQh = (__half*)(smem);
    __half* sQl = (__half*)(smem + 18432);
    __half* sKh = (__half*)(smem + 36864);
    __half* sKl = (__half*)(smem + 55296);
    __half* sVh = (__half*)(smem + 73728);
    const uint32_t uQh = smem_u32(sQh), uQl = smem_u32(sQl);
    const uint32_t uKh = smem_u32(sKh), uKl = smem_u32(sKl);
    const uint32_t uVh = smem_u32(sVh);

    const int q0 = blockIdx.x * 128;
    const int hb = blockIdx.y;
    const int h = hb / B, b = hb % B;

    const __half* Qh_g = g_qkvb_hi + ((size_t)0 * H + h) * BS * E + (size_t)(b * S + q0) * E;
    const __half* Ql_g = g_qkvb_lo + ((size_t)0 * H + h) * BS * E + (size_t)(b * S + q0) * E;
    const __half* Kh_g = g_qkvb_hi + ((size_t)1 * H + h) * BS * E + (size_t)b * S * E;
    const __half* Kl_g = g_qkvb_lo + ((size_t)1 * H + h) * BS * E + (size_t)b * S * E;
    const __half* Vh_g = g_qkvb_hi + ((size_t)2 * H + h) * BS * E + (size_t)b * S * E;
    const float* mask = mask_all + (size_t)(h * B + b) * S * S;

    const int t = threadIdx.x, lane = t & 31, wid = t >> 5;
    const int g = lane >> 2, j2 = (lane & 3) * 2;
    const int r0 = wid * 16;

    // Q tiles -> smem -> register fragments (hoisted for whole kernel)
    load_tile_pad(Qh_g, E, sQh, t);
    load_tile_pad(Ql_g, E, sQl, t);
    __syncthreads();
    uint32_t qh[4][4], ql[4][4];
    {
        const uint32_t ao = (uint32_t)(r0 + (lane & 15)) * 144 + ((lane & 16) >> 1) * 2;
        #pragma unroll
        for (int ks = 0; ks < 4; ks++) {
            ldsm4(qh[ks], uQh + ao + ks * 32);
            ldsm4(ql[ks], uQl + ao + ks * 32);
        }
    }

    float m_a = -INFINITY, m_b = -INFINITY, l_a = 0.f, l_b = 0.f;
    float o[8][4];
    #pragma unroll
    for (int et = 0; et < 8; et++)
        o[et][0] = o[et][1] = o[et][2] = o[et][3] = 0.f;

    const uint32_t kb_off = (uint32_t)((lane & 7) + ((lane & 16) >> 1)) * 144 + (lane & 8) * 2;
    const uint32_t vb_off = (uint32_t)(lane & 15) * 144 + ((lane & 16) >> 1) * 2;

    #pragma unroll 1
    for (int j0 = 0; j0 < S; j0 += 128) {
        __syncthreads();
        load_tile_pad(Kh_g + (size_t)j0 * E, E, sKh, t);
        load_tile_pad(Kl_g + (size_t)j0 * E, E, sKl, t);
        load_tile_pad(Vh_g + (size_t)j0 * E, E, sVh, t);
        __syncthreads();

        // ---- mask L2 prefetch (overlaps S-MMA block) ----
        const float* mra = mask + (size_t)(q0 + r0 + g) * S + j0 + j2;
        const float* mrb = mra + 8 * S;
        #pragma unroll
        for (int q8 = 0; q8 < 4; q8++) {
            asm volatile("prefetch.global.L2 [%0];" :: "l"(mra + q8 * 32));
            asm volatile("prefetch.global.L2 [%0];" :: "l"(mrb + q8 * 32));
        }

        // ---- S = Q K^T (3-product) ----
        float s[16][4];
        #pragma unroll
        for (int nt = 0; nt < 16; nt++)
            s[nt][0] = s[nt][1] = s[nt][2] = s[nt][3] = 0.f;

        #pragma unroll
        for (int ks = 0; ks < 4; ks++) {
            #pragma unroll
            for (int np = 0; np < 8; np++) {
                uint32_t bh[4], bl[4];
                const uint32_t bo = kb_off + np * 16 * 144 + ks * 32;
                ldsm4(bh, uKh + bo);
                ldsm4(bl, uKl + bo);
                mma16816(s[2*np],   qh[ks], bh[0], bh[1]);
                mma16816(s[2*np],   qh[ks], bl[0], bl[1]);
                mma16816(s[2*np],   ql[ks], bh[0], bh[1]);
                mma16816(s[2*np+1], qh[ks], bh[2], bh[3]);
                mma16816(s[2*np+1], qh[ks], bl[2], bl[3]);
                mma16816(s[2*np+1], ql[ks], bh[2], bh[3]);
            }
        }

        // ---- additive mask ----
        #pragma unroll
        for (int nt = 0; nt < 16; nt++) {
            float2 ma = *(const float2*)(mra + nt * 8);
            float2 mb = *(const float2*)(mrb + nt * 8);
            s[nt][0] += ma.x; s[nt][1] += ma.y;
            s[nt][2] += mb.x; s[nt][3] += mb.y;
        }

        // ---- online softmax (rows g and g+8 of this warp's 16) ----
        float mxa = -INFINITY, mxb = -INFINITY;
        #pragma unroll
        for (int nt = 0; nt < 16; nt++) {
            mxa = fmaxf(mxa, fmaxf(s[nt][0], s[nt][1]));
            mxb = fmaxf(mxb, fmaxf(s[nt][2], s[nt][3]));
        }
        mxa = fmaxf(mxa, __shfl_xor_sync(0xffffffffu, mxa, 1));
        mxa = fmaxf(mxa, __shfl_xor_sync(0xffffffffu, mxa, 2));
        mxb = fmaxf(mxb, __shfl_xor_sync(0xffffffffu, mxb, 1));
        mxb = fmaxf(mxb, __shfl_xor_sync(0xffffffffu, mxb, 2));

        const float mna = fmaxf(m_a, mxa), mnb = fmaxf(m_b, mxb);
        const float aa = __expf(m_a - mna), ab = __expf(m_b - mnb);
        float sa = 0.f, sb2 = 0.f;
        #pragma unroll
        for (int nt = 0; nt < 16; nt++) {
            s[nt][0] = __expf(s[nt][0] - mna); sa += s[nt][0];
            s[nt][1] = __expf(s[nt][1] - mna); sa += s[nt][1];
            s[nt][2] = __expf(s[nt][2] - mnb); sb2 += s[nt][2];
            s[nt][3] = __expf(s[nt][3] - mnb); sb2 += s[nt][3];
        }
        sa  += __shfl_xor_sync(0xffffffffu, sa, 1);
        sa  += __shfl_xor_sync(0xffffffffu, sa, 2);
        sb2 += __shfl_xor_sync(0xffffffffu, sb2, 1);
        sb2 += __shfl_xor_sync(0xffffffffu, sb2, 2);
        l_a = l_a * aa + sa; l_b = l_b * ab + sb2;
        m_a = mna; m_b = mnb;
        #pragma unroll
        for (int et = 0; et < 8; et++) {
            o[et][0] *= aa; o[et][1] *= aa;
            o[et][2] *= ab; o[et][3] *= ab;
        }

        // ---- O += P V (P split hi/lo in registers; V hi only: 2-product) ----
        #pragma unroll
        for (int ks2 = 0; ks2 < 8; ks2++) {
            const int nt0 = 2 * ks2, nt1 = nt0 + 1;
            uint32_t a_hi[4], a_lo[4];
            split2(s[nt0][0], s[nt0][1], a_hi[0], a_lo[0]);
            split2(s[nt0][2], s[nt0][3], a_hi[1], a_lo[1]);
            split2(s[nt1][0], s[nt1][1], a_hi[2], a_lo[2]);
            split2(s[nt1][2], s[nt1][3], a_hi[3], a_lo[3]);
            #pragma unroll
            for (int ep = 0; ep < 4; ep++) {
                uint32_t vh[4];
                const uint32_t vo = vb_off + ks2 * 16 * 144 + ep * 32;
                ldsm4t(vh, uVh + vo);
                mma16816(o[2*ep],   a_hi, vh[0], vh[1]);
                mma16816(o[2*ep],   a_lo, vh[0], vh[1]);
                mma16816(o[2*ep+1], a_hi, vh[2], vh[3]);
                mma16816(o[2*ep+1], a_lo, vh[2], vh[3]);
            }
        }
    }

    // ---- epilogue: normalize, split hi/lo, concat-head layout ----
    const float ia = 1.f / l_a, ib = 1.f / l_b;
    const int rowA = q0 + r0 + g, rowB = rowA + 8;
    #pragma unroll
    for (int et = 0; et < 8; et++) {
        const size_t col = (size_t)h * E + et * 8 + j2;
        uint32_t hi, lo;
        split2(o[et][0] * ia, o[et][1] * ia, hi, lo);
        *(uint32_t*)(g_att_hi + (size_t)(b * S + rowA) * D + col) = hi;
        *(uint32_t*)(g_att_lo + (size_t)(b * S + rowA) * D + col) = lo;
        split2(o[et][2] * ib, o[et][3] * ib, hi, lo);
        *(uint32_t*)(g_att_hi + (size_t)(b * S + rowB) * D + col) = hi;
        *(uint32_t*)(g_att_lo + (size_t)(b * S + rowB) * D + col) = lo;
    }
}

// ======================= Launch =======================
extern "C" void kernel_launch(void* const* d_in, const int* in_sizes, int n_in,
                              void* d_out, int out_size)
{
    const float* x    = (const float*)d_in[0];
    const float* mask = (const float*)d_in[1];
    const float* Wq   = (const float*)d_in[2];
    const float* bq   = (const float*)d_in[3];
    const float* Wk   = (const float*)d_in[4];
    const float* bk   = (const float*)d_in[5];
    const float* Wv   = (const float*)d_in[6];
    const float* bv   = (const float*)d_in[7];
    const float* Wo   = (const float*)d_in[8];
    const float* bo   = (const float*)d_in[9];

    const int smem_gemm = 4 * 128 * PAD * 2;   // 73,728 B  (2 CTAs/SM)
    const int smem_attn = 5 * 128 * PAD * 2;   // 92,160 B
    cudaFuncSetAttribute(qkv_mma_kernel,  cudaFuncAttributeMaxDynamicSharedMemorySize, smem_gemm);
    cudaFuncSetAttribute(proj_mma_kernel, cudaFuncAttributeMaxDynamicSharedMemorySize, smem_gemm);
    cudaFuncSetAttribute(attn_kernel,     cudaFuncAttributeMaxDynamicSharedMemorySize, smem_attn);

    const int prep_n = XN + 3 * HED + D * D;
    prep_kernel<<< (prep_n + 255) / 256, 256 >>>(x, Wq, Wk, Wv, Wo);

    qkv_mma_kernel <<< dim3(BS / 128, 3 * (H / 2)), 256, smem_gemm >>>(bq, bk, bv);
    attn_kernel    <<< dim3(S / 128, H * B), 256, smem_attn >>>(mask);
    proj_mma_kernel<<< dim3(BS / 128, D / 128), 256, smem_gemm >>>(bo, (float*)d_out);
}

// round 7
// speedup vs baseline: 1.3281x; 1.2757x over previous
#include <cuda_runtime.h>
#include <cuda_fp16.h>
#include <math.h>
#include <stdint.h>

#define B 2
#define S 2048
#define D 768
#define H 12
#define E 64
#define BS (B*S)   // 4096
#define XN (BS*D)
#define HED (H*E*D)

// ---- scratch (static device globals; no runtime allocation) ----
__device__ __align__(16) __half g_x_hi[(size_t)BS * D];
__device__ __align__(16) __half g_x_lo[(size_t)BS * D];
__device__ __align__(16) __half g_wt_hi[(size_t)3 * H * E * D]; // [which][h*E+e][k]
__device__ __align__(16) __half g_wt_lo[(size_t)3 * H * E * D];
__device__ __align__(16) __half g_wo_hi[(size_t)D * D];         // [n][k]
__device__ __align__(16) __half g_wo_lo[(size_t)D * D];
__device__ __align__(16) __half g_qkvb_hi[(size_t)3 * H * BS * E]; // [which][h][b*S+s][e]
__device__ __align__(16) __half g_qkvb_lo[(size_t)3 * H * BS * E];
__device__ __align__(16) __half g_att_hi[(size_t)BS * D];       // [b*S+s][h*E+e]
__device__ __align__(16) __half g_att_lo[(size_t)BS * D];

// ======================= helpers =======================
__device__ __forceinline__ uint32_t smem_u32(const void* p) {
    uint32_t a;
    asm("{ .reg .u64 t; cvta.to.shared.u64 t, %1; cvt.u32.u64 %0, t; }" : "=r"(a) : "l"(p));
    return a;
}
// swizzled offset within a tile of 128-byte rows: row r, 16B-chunk c16 (0..7)
__device__ __forceinline__ uint32_t sw_off(uint32_t r, uint32_t c16) {
    return (r << 7) + (((c16 ^ r) & 7u) << 4);
}
__device__ __forceinline__ void ldsm4(uint32_t* r, uint32_t a) {
    asm volatile("ldmatrix.sync.aligned.m8n8.x4.shared.b16 {%0,%1,%2,%3}, [%4];"
        : "=r"(r[0]), "=r"(r[1]), "=r"(r[2]), "=r"(r[3]) : "r"(a));
}
__device__ __forceinline__ void ldsm4t(uint32_t* r, uint32_t a) {
    asm volatile("ldmatrix.sync.aligned.m8n8.x4.trans.shared.b16 {%0,%1,%2,%3}, [%4];"
        : "=r"(r[0]), "=r"(r[1]), "=r"(r[2]), "=r"(r[3]) : "r"(a));
}
__device__ __forceinline__ void mma16816(float* c, const uint32_t* a, uint32_t b0, uint32_t b1) {
    asm volatile("mma.sync.aligned.m16n8k16.row.col.f32.f16.f16.f32 "
        "{%0,%1,%2,%3}, {%4,%5,%6,%7}, {%8,%9}, {%0,%1,%2,%3};"
        : "+f"(c[0]), "+f"(c[1]), "+f"(c[2]), "+f"(c[3])
        : "r"(a[0]), "r"(a[1]), "r"(a[2]), "r"(a[3]), "r"(b0), "r"(b1));
}
__device__ __forceinline__ void split2(float x, float y, uint32_t& hi, uint32_t& lo) {
    __half2 h = __floats2half2_rn(x, y);
    float hx = __low2float(h), hy = __high2float(h);
    __half2 l = __floats2half2_rn(x - hx, y - hy);
    hi = *(uint32_t*)&h; lo = *(uint32_t*)&l;
}
#define CP_COMMIT()  asm volatile("cp.async.commit_group;" ::: "memory")
#define CP_WAIT1()   asm volatile("cp.async.wait_group 1;" ::: "memory")
#define CP_WAIT0()   asm volatile("cp.async.wait_group 0;" ::: "memory")

// cp.async a tile of R rows x 64 fp16 (128B/row) into swizzled smem (256 threads)
template<int R>
__device__ __forceinline__ void cpa_tile(const __half* __restrict__ g, int ldg,
                                         uint32_t sdst, int t)
{
    #pragma unroll
    for (int i = 0; i < (R * 8) / 256; i++) {
        int f = i * 256 + t;
        uint32_t r = (uint32_t)(f >> 3), c = (uint32_t)(f & 7);
        asm volatile("cp.async.cg.shared.global [%0], [%1], 16;"
            :: "r"(sdst + sw_off(r, c)), "l"(g + (size_t)r * ldg + c * 8));
    }
}

// ======================= fused prep: fp32 -> fp16 hi/lo =======================
__global__ void prep_kernel(const float* __restrict__ x,
                            const float* __restrict__ Wq, const float* __restrict__ Wk,
                            const float* __restrict__ Wv, const float* __restrict__ Wo)
{
    int i = blockIdx.x * 256 + threadIdx.x;
    float v;
    __half *dh, *dl;
    if (i < XN) {
        v = x[i];
        dh = g_x_hi + i; dl = g_x_lo + i;
    } else if (i < XN + 3 * HED) {
        int i2 = i - XN;
        int w = i2 / HED, r2 = i2 % HED;
        int k = r2 % D, row = r2 / D;
        int h = row / E, e = row % E;
        const float* W = (w == 0) ? Wq : (w == 1) ? Wk : Wv;
        v = W[((size_t)h * D + k) * E + e];
        dh = g_wt_hi + i2; dl = g_wt_lo + i2;
    } else if (i < XN + 3 * HED + D * D) {
        int i3 = i - XN - 3 * HED;
        int k = i3 % D, n = i3 / D;
        v = Wo[(size_t)k * D + n];
        dh = g_wo_hi + i3; dl = g_wo_lo + i3;
    } else return;
    __half hv = __float2half_rn(v);
    *dh = hv;
    *dl = __float2half_rn(v - __half2float(hv));
}

// ======================= GEMM core: CTA 128x64, 8 warps (4x2), warp tile 32x32 ==========
// 2-stage cp.async pipeline; stage = Ah(16K), Al(16K), Bh(8K), Bl(8K) = 48K.
struct Acc64 { float a[2][4][4]; };
#define G_STAGE 49152

__device__ __forceinline__ void gemm_core(
    const __half* __restrict__ Ah_g, const __half* __restrict__ Al_g, int lda,
    const __half* __restrict__ Bh_g, const __half* __restrict__ Bl_g, int ldb,
    uint32_t sb, int t, Acc64& C, bool use_blo)
{
    const int lane = t & 31, wid = t >> 5;
    const int wm = (wid >> 1) * 32, wn = (wid & 1) * 32;

    // prefetch chunk 0 -> stage 0
    cpa_tile<128>(Ah_g, lda, sb, t);
    cpa_tile<128>(Al_g, lda, sb + 16384, t);
    cpa_tile<64>(Bh_g, ldb, sb + 32768, t);
    if (use_blo) cpa_tile<64>(Bl_g, ldb, sb + 40960, t);
    CP_COMMIT();

    const uint32_t a_row  = (uint32_t)(wm + (lane & 15));
    const uint32_t a_chi  = (uint32_t)((lane >> 4) & 1);
    const uint32_t b_row0 = (uint32_t)(wn + (lane & 7) + ((lane & 16) >> 1));
    const uint32_t b_chi  = (uint32_t)((lane >> 3) & 1);

    #pragma unroll 1
    for (int c = 0; c < 12; c++) {
        if (c + 1 < 12) {
            uint32_t st = sb + (uint32_t)((c + 1) & 1) * G_STAGE;
            cpa_tile<128>(Ah_g + (c + 1) * 64, lda, st, t);
            cpa_tile<128>(Al_g + (c + 1) * 64, lda, st + 16384, t);
            cpa_tile<64>(Bh_g + (c + 1) * 64, ldb, st + 32768, t);
            if (use_blo) cpa_tile<64>(Bl_g + (c + 1) * 64, ldb, st + 40960, t);
            CP_COMMIT();
            CP_WAIT1();
        } else {
            CP_WAIT0();
        }
        __syncthreads();

        const uint32_t cs = sb + (uint32_t)(c & 1) * G_STAGE;
        const uint32_t uAh = cs, uAl = cs + 16384, uBh = cs + 32768, uBl = cs + 40960;

        #pragma unroll
        for (int ks = 0; ks < 4; ks++) {
            const uint32_t c16a = (uint32_t)(ks * 2) + a_chi;
            const uint32_t c16b = (uint32_t)(ks * 2) + b_chi;
            uint32_t ah0[4], ah1[4], al0[4], al1[4];
            ldsm4(ah0, uAh + sw_off(a_row, c16a));
            ldsm4(ah1, uAh + sw_off(a_row + 16, c16a));
            ldsm4(al0, uAl + sw_off(a_row, c16a));
            ldsm4(al1, uAl + sw_off(a_row + 16, c16a));
            #pragma unroll
            for (int np = 0; np < 2; np++) {
                uint32_t bh[4];
                ldsm4(bh, uBh + sw_off(b_row0 + np * 16, c16b));
                mma16816(C.a[0][2*np],   ah0, bh[0], bh[1]);
                mma16816(C.a[0][2*np+1], ah0, bh[2], bh[3]);
                mma16816(C.a[1][2*np],   ah1, bh[0], bh[1]);
                mma16816(C.a[1][2*np+1], ah1, bh[2], bh[3]);
                mma16816(C.a[0][2*np],   al0, bh[0], bh[1]);
                mma16816(C.a[0][2*np+1], al0, bh[2], bh[3]);
                mma16816(C.a[1][2*np],   al1, bh[0], bh[1]);
                mma16816(C.a[1][2*np+1], al1, bh[2], bh[3]);
                if (use_blo) {
                    uint32_t bl[4];
                    ldsm4(bl, uBl + sw_off(b_row0 + np * 16, c16b));
                    mma16816(C.a[0][2*np],   ah0, bl[0], bl[1]);
                    mma16816(C.a[0][2*np+1], ah0, bl[2], bl[3]);
                    mma16816(C.a[1][2*np],   ah1, bl[0], bl[1]);
                    mma16816(C.a[1][2*np+1], ah1, bl[2], bl[3]);
                }
            }
        }
        __syncthreads();
    }
}

// ======================= QKV GEMM kernel: CTA 128(m) x 64(one head) =======================
__global__ __launch_bounds__(256, 2) void qkv_mma_kernel(
    const float* __restrict__ bq, const float* __restrict__ bk, const float* __restrict__ bv)
{
    extern __shared__ __align__(16) char smem[];
    const uint32_t sb = smem_u32(smem);
    const int t = threadIdx.x, lane = t & 31, wid = t >> 5;
    const int m0 = blockIdx.x * 128;
    const int zz = blockIdx.y;             // 0..35
    const int which = zz / H;
    const int h = zz % H;

    Acc64 C;
    #pragma unroll
    for (int i = 0; i < 2; i++)
        #pragma unroll
        for (int j = 0; j < 4; j++)
            C.a[i][j][0] = C.a[i][j][1] = C.a[i][j][2] = C.a[i][j][3] = 0.f;

    gemm_core(g_x_hi + (size_t)m0 * D, g_x_lo + (size_t)m0 * D, D,
              g_wt_hi + ((size_t)which * H + h) * E * D,
              g_wt_lo + ((size_t)which * H + h) * E * D, D,
              sb, t, C, which != 2);   // V: 2-product

    const float* bias = (which == 0) ? bq : (which == 1) ? bk : bv;
    const int g = lane >> 2, j2 = (lane & 3) * 2;
    const int wm = (wid >> 1) * 32, wn = (wid & 1) * 32;
    const size_t obase = ((size_t)which * H + h) * BS * E;

    #pragma unroll
    for (int mi = 0; mi < 2; mi++) {
        const int mA = m0 + wm + mi * 16 + g;
        #pragma unroll
        for (int nt = 0; nt < 4; nt++) {
            const int e = wn + nt * 8 + j2;
            const float b0f = bias[h * E + e], b1f = bias[h * E + e + 1];
            uint32_t hi, lo;
            split2(C.a[mi][nt][0] + b0f, C.a[mi][nt][1] + b1f, hi, lo);
            *(uint32_t*)(g_qkvb_hi + obase + (size_t)mA * E + e) = hi;
            *(uint32_t*)(g_qkvb_lo + obase + (size_t)mA * E + e) = lo;
            split2(C.a[mi][nt][2] + b0f, C.a[mi][nt][3] + b1f, hi, lo);
            *(uint32_t*)(g_qkvb_hi + obase + (size_t)(mA + 8) * E + e) = hi;
            *(uint32_t*)(g_qkvb_lo + obase + (size_t)(mA + 8) * E + e) = lo;
        }
    }
}

// ======================= output projection: CTA 128(m) x 64(n), 2-product ===============
__global__ __launch_bounds__(256, 2) void proj_mma_kernel(
    const float* __restrict__ bo, float* __restrict__ out)
{
    extern __shared__ __align__(16) char smem[];
    const uint32_t sb = smem_u32(smem);
    const int t = threadIdx.x, lane = t & 31, wid = t >> 5;
    const int m0 = blockIdx.x * 128;
    const int n0 = blockIdx.y * 64;

    Acc64 C;
    #pragma unroll
    for (int i = 0; i < 2; i++)
        #pragma unroll
        for (int j = 0; j < 4; j++)
            C.a[i][j][0] = C.a[i][j][1] = C.a[i][j][2] = C.a[i][j][3] = 0.f;

    gemm_core(g_att_hi + (size_t)m0 * D, g_att_lo + (size_t)m0 * D, D,
              g_wo_hi + (size_t)n0 * D, g_wo_lo + (size_t)n0 * D, D,
              sb, t, C, false);

    const int g = lane >> 2, j2 = (lane & 3) * 2;
    const int wm = (wid >> 1) * 32, wn = (wid & 1) * 32;

    #pragma unroll
    for (int mi = 0; mi < 2; mi++) {
        const int mA = m0 + wm + mi * 16 + g;
        #pragma unroll
        for (int nt = 0; nt < 4; nt++) {
            const int n = n0 + wn + nt * 8 + j2;
            const float b0f = bo[n], b1f = bo[n + 1];
            float2 v0 = { C.a[mi][nt][0] + b0f, C.a[mi][nt][1] + b1f };
            float2 v1 = { C.a[mi][nt][2] + b0f, C.a[mi][nt][3] + b1f };
            *(float2*)(out + (size_t)mA * D + n) = v0;
            *(float2*)(out + (size_t)(mA + 8) * D + n) = v1;
        }
    }
}

// ======================= flash attention =======================
// 256 threads, 8 warps x 16 q-rows = 128-row q tile; kv chunks of 64, 32 chunks.
// smem: Q region 32K resident (Qh 0, Ql 16K); 2 stages x {Kh 8K? no: Kh 8K, Kl 8K, Vh 8K}=24K
// at 32768 + st*24576. Total 81920 B.
#define A_STAGE 24576
#define A_KV    32768
__global__ __launch_bounds__(256, 2) void attn_kernel(const float* __restrict__ mask_all)
{
    extern __shared__ __align__(16) char smem[];
    const uint32_t sb = smem_u32(smem);

    const int q0 = blockIdx.x * 128;
    const int hb = blockIdx.y;
    const int h = hb / B, b = hb % B;

    const __half* Qh_g = g_qkvb_hi + ((size_t)0 * H + h) * BS * E + (size_t)(b * S + q0) * E;
    const __half* Ql_g = g_qkvb_lo + ((size_t)0 * H + h) * BS * E + (size_t)(b * S + q0) * E;
    const __half* Kh_g = g_qkvb_hi + ((size_t)1 * H + h) * BS * E + (size_t)b * S * E;
    const __half* Kl_g = g_qkvb_lo + ((size_t)1 * H + h) * BS * E + (size_t)b * S * E;
    const __half* Vh_g = g_qkvb_hi + ((size_t)2 * H + h) * BS * E + (size_t)b * S * E;
    const float* mask = mask_all + (size_t)(h * B + b) * S * S;

    const int t = threadIdx.x, lane = t & 31, wid = t >> 5;
    const int g = lane >> 2, j2 = (lane & 3) * 2;
    const int r0 = wid * 16;

    // Q -> resident smem region (group 0)
    cpa_tile<128>(Qh_g, E, sb, t);
    cpa_tile<128>(Ql_g, E, sb + 16384, t);
    CP_COMMIT();
    // kv chunk 0 -> stage 0 (group 1)
    cpa_tile<64>(Kh_g, E, sb + A_KV, t);
    cpa_tile<64>(Kl_g, E, sb + A_KV + 8192, t);
    cpa_tile<64>(Vh_g, E, sb + A_KV + 16384, t);
    CP_COMMIT();

    float m_a = -INFINITY, m_b = -INFINITY, l_a = 0.f, l_b = 0.f;
    float o[8][4];
    #pragma unroll
    for (int et = 0; et < 8; et++)
        o[et][0] = o[et][1] = o[et][2] = o[et][3] = 0.f;

    const uint32_t a_row  = (uint32_t)(r0 + (lane & 15));
    const uint32_t a_chi  = (uint32_t)((lane >> 4) & 1);
    const uint32_t b_row0 = (uint32_t)((lane & 7) + ((lane & 16) >> 1));
    const uint32_t b_chi  = (uint32_t)((lane >> 3) & 1);
    const uint32_t v_row  = (uint32_t)(lane & 15);
    const uint32_t v_chi  = (uint32_t)((lane >> 4) & 1);

    #pragma unroll 1
    for (int jc = 0; jc < 32; jc++) {
        const int j0 = jc * 64;

        // mask loads first: they initialize the S accumulators and overlap the pipe wait
        float s[8][4];
        const float* mra = mask + (size_t)(q0 + r0 + g) * S + j0 + j2;
        const float* mrb = mra + 8 * S;
        #pragma unroll
        for (int nt = 0; nt < 8; nt++) {
            float2 ma = *(const float2*)(mra + nt * 8);
            float2 mb = *(const float2*)(mrb + nt * 8);
            s[nt][0] = ma.x; s[nt][1] = ma.y; s[nt][2] = mb.x; s[nt][3] = mb.y;
        }

        if (jc + 1 < 32) {
            const uint32_t ns = sb + A_KV + (uint32_t)((jc + 1) & 1) * A_STAGE;
            const size_t go = (size_t)(j0 + 64) * E;
            cpa_tile<64>(Kh_g + go, E, ns, t);
            cpa_tile<64>(Kl_g + go, E, ns + 8192, t);
            cpa_tile<64>(Vh_g + go, E, ns + 16384, t);
            CP_COMMIT();
            CP_WAIT1();
        } else {
            CP_WAIT0();
        }
        __syncthreads();

        const uint32_t cs = sb + A_KV + (uint32_t)(jc & 1) * A_STAGE;
        const uint32_t uKh = cs, uKl = cs + 8192, uVh = cs + 16384;

        // ---- S += Q K^T (3-product; Q frags re-read from resident smem) ----
        #pragma unroll
        for (int ks = 0; ks < 4; ks++) {
            const uint32_t c16a = (uint32_t)(ks * 2) + a_chi;
            const uint32_t c16b = (uint32_t)(ks * 2) + b_chi;
            uint32_t qh[4], ql[4];
            ldsm4(qh, sb + sw_off(a_row, c16a));
            ldsm4(ql, sb + 16384 + sw_off(a_row, c16a));
            #pragma unroll
            for (int np = 0; np < 4; np++) {
                uint32_t bh[4], bl[4];
                const uint32_t bo_ = sw_off(b_row0 + np * 16, c16b);
                ldsm4(bh, uKh + bo_);
                ldsm4(bl, uKl + bo_);
                mma16816(s[2*np],   qh, bh[0], bh[1]);
                mma16816(s[2*np+1], qh, bh[2], bh[3]);
                mma16816(s[2*np],   qh, bl[0], bl[1]);
                mma16816(s[2*np+1], qh, bl[2], bl[3]);
                mma16816(s[2*np],   ql, bh[0], bh[1]);
                mma16816(s[2*np+1], ql, bh[2], bh[3]);
            }
        }

        // ---- online softmax (rows g and g+8 of this warp's 16) ----
        float mxa = -INFINITY, mxb = -INFINITY;
        #pragma unroll
        for (int nt = 0; nt < 8; nt++) {
            mxa = fmaxf(mxa, fmaxf(s[nt][0], s[nt][1]));
            mxb = fmaxf(mxb, fmaxf(s[nt][2], s[nt][3]));
        }
        mxa = fmaxf(mxa, __shfl_xor_sync(0xffffffffu, mxa, 1));
        mxa = fmaxf(mxa, __shfl_xor_sync(0xffffffffu, mxa, 2));
        mxb = fmaxf(mxb, __shfl_xor_sync(0xffffffffu, mxb, 1));
        mxb = fmaxf(mxb, __shfl_xor_sync(0xffffffffu, mxb, 2));

        const float mna = fmaxf(m_a, mxa), mnb = fmaxf(m_b, mxb);
        const float aa = __expf(m_a - mna), ab = __expf(m_b - mnb);
        float sa = 0.f, sb2 = 0.f;
        #pragma unroll
        for (int nt = 0; nt < 8; nt++) {
            s[nt][0] = __expf(s[nt][0] - mna); sa += s[nt][0];
            s[nt][1] = __expf(s[nt][1] - mna); sa += s[nt][1];
            s[nt][2] = __expf(s[nt][2] - mnb); sb2 += s[nt][2];
            s[nt][3] = __expf(s[nt][3] - mnb); sb2 += s[nt][3];
        }
        sa  += __shfl_xor_sync(0xffffffffu, sa, 1);
        sa  += __shfl_xor_sync(0xffffffffu, sa, 2);
        sb2 += __shfl_xor_sync(0xffffffffu, sb2, 1);
        sb2 += __shfl_xor_sync(0xffffffffu, sb2, 2);
        l_a = l_a * aa + sa; l_b = l_b * ab + sb2;
        m_a = mna; m_b = mnb;
        #pragma unroll
        for (int et = 0; et < 8; et++) {
            o[et][0] *= aa; o[et][1] *= aa;
            o[et][2] *= ab; o[et][3] *= ab;
        }

        // ---- O += P V (P split hi/lo in regs; 2-product) ----
        #pragma unroll
        for (int ks2 = 0; ks2 < 4; ks2++) {
            const int nt0 = 2 * ks2, nt1 = nt0 + 1;
            uint32_t a_hi[4], a_lo[4];
            split2(s[nt0][0], s[nt0][1], a_hi[0], a_lo[0]);
            split2(s[nt0][2], s[nt0][3], a_hi[1], a_lo[1]);
            split2(s[nt1][0], s[nt1][1], a_hi[2], a_lo[2]);
            split2(s[nt1][2], s[nt1][3], a_hi[3], a_lo[3]);
            #pragma unroll
            for (int ep = 0; ep < 4; ep++) {
                uint32_t vh[4];
                ldsm4t(vh, uVh + sw_off(v_row + ks2 * 16, (uint32_t)(ep * 2) + v_chi));
                mma16816(o[2*ep],   a_hi, vh[0], vh[1]);
                mma16816(o[2*ep+1], a_hi, vh[2], vh[3]);
                mma16816(o[2*ep],   a_lo, vh[0], vh[1]);
                mma16816(o[2*ep+1], a_lo, vh[2], vh[3]);
            }
        }
        __syncthreads();
    }

    // ---- epilogue: normalize, split hi/lo, concat-head layout ----
    const float ia = 1.f / l_a, ib = 1.f / l_b;
    const int rowA = q0 + r0 + g, rowB = rowA + 8;
    #pragma unroll
    for (int et = 0; et < 8; et++) {
        const size_t col = (size_t)h * E + et * 8 + j2;
        uint32_t hi, lo;
        split2(o[et][0] * ia, o[et][1] * ia, hi, lo);
        *(uint32_t*)(g_att_hi + (size_t)(b * S + rowA) * D + col) = hi;
        *(uint32_t*)(g_att_lo + (size_t)(b * S + rowA) * D + col) = lo;
        split2(o[et][2] * ib, o[et][3] * ib, hi, lo);
        *(uint32_t*)(g_att_hi + (size_t)(b * S + rowB) * D + col) = hi;
        *(uint32_t*)(g_att_lo + (size_t)(b * S + rowB) * D + col) = lo;
    }
}

// ======================= Launch =======================
extern "C" void kernel_launch(void* const* d_in, const int* in_sizes, int n_in,
                              void* d_out, int out_size)
{
    const float* x    = (const float*)d_in[0];
    const float* mask = (const float*)d_in[1];
    const float* Wq   = (const float*)d_in[2];
    const float* bq   = (const float*)d_in[3];
    const float* Wk   = (const float*)d_in[4];
    const float* bk   = (const float*)d_in[5];
    const float* Wv   = (const float*)d_in[6];
    const float* bv   = (const float*)d_in[7];
    const float* Wo   = (const float*)d_in[8];
    const float* bo   = (const float*)d_in[9];

    const int smem_gemm = 2 * G_STAGE;          // 98,304 B
    const int smem_attn = A_KV + 2 * A_STAGE;   // 81,920 B
    cudaFuncSetAttribute(qkv_mma_kernel,  cudaFuncAttributeMaxDynamicSharedMemorySize, smem_gemm);
    cudaFuncSetAttribute(proj_mma_kernel, cudaFuncAttributeMaxDynamicSharedMemorySize, smem_gemm);
    cudaFuncSetAttribute(attn_kernel,     cudaFuncAttributeMaxDynamicSharedMemorySize, smem_attn);

    const int prep_n = XN + 3 * HED + D * D;
    prep_kernel<<< (prep_n + 255) / 256, 256 >>>(x, Wq, Wk, Wv, Wo);

    qkv_mma_kernel <<< dim3(BS / 128, 3 * H), 256, smem_gemm >>>(bq, bk, bv);
    attn_kernel    <<< dim3(S / 128, H * B), 256, smem_attn >>>(mask);
    proj_mma_kernel<<< dim3(BS / 128, D / 64), 256, smem_gemm >>>(bo, (float*)d_out);
}